// round 2
// baseline (speedup 1.0000x reference)
#include <cuda_runtime.h>
#include <cstdint>

// Problem constants
#define NA 512
#define NB 512
#define ND 128      // NODE_DIM
#define ED 128      // EDGE_DIM
#define EIN 256     // 2*EDGE_DIM (edge_embeds last dim)

// Edge kernel tiling
#define TA 8
#define TB 16
#define MT 128      // TA*TB edges per block
#define NT 128
#define KT 16

// Scratch (device globals; no allocations allowed)
__device__ float g_A1[NA * ED];                 // na@Wa + be1
__device__ float g_B1[NB * ED];                 // nb@Wb
__device__ float g_sumA_part[(size_t)NA * 32 * ED];  // [a][b_tile(32)][d]
__device__ float g_sumB_part[(size_t)NB * 64 * ED];  // [b][a_tile(64)][d]

// ---------------------------------------------------------------------------
// Kernel 1: A1[r] = nodes_a[r] @ We1[0:128] + be1 ;  B1[r] = nodes_b[r] @ We1[128:256]
// grid 1024 blocks x 128 threads
// ---------------------------------------------------------------------------
__global__ void k_pre(const float* __restrict__ na, const float* __restrict__ nb,
                      const float* __restrict__ We1, const float* __restrict__ be1) {
    int r = blockIdx.x;
    int d = threadIdx.x;
    bool isA = (r < NA);
    int rr = isA ? r : r - NA;
    __shared__ float xs[ND];
    xs[d] = (isA ? na : nb)[rr * ND + d];
    __syncthreads();
    const float* W = We1 + (isA ? 0 : ND * ED);
    float acc = isA ? be1[d] : 0.0f;
#pragma unroll 8
    for (int k = 0; k < ND; k++) acc = fmaf(xs[k], W[k * ED + d], acc);
    if (isA) g_A1[rr * ED + d] = acc;
    else     g_B1[rr * ED + d] = acc;
}

// ---------------------------------------------------------------------------
// Kernel 2: main edge pipeline.
// Block = (16,16) threads, tile = TA(8) a's x TB(16) b's = 128 edge rows.
// GEMM1: h = relu(E_tile @ We + A1 + B1)  [128 x 128], K=256
// GEMM2: L = relu(h @ We2 + be2)          [128 x 128], K=128
// Writes edge_latent + deterministic partial sums (row/col) to scratch.
// ---------------------------------------------------------------------------
__global__ __launch_bounds__(256, 1)
void k_edge(const float* __restrict__ E, const float* __restrict__ We1,
            const float* __restrict__ We2, const float* __restrict__ be2,
            float* __restrict__ out) {
    extern __shared__ float sm[];
    float* sWe2 = sm;                    // 128*128        = 16384 floats
    float* sL   = sWe2 + 16384;          // 128*132        = 16896 floats (h, then latent)
    float* sAT  = sL + 16896;            // 16*136         = 2176  floats
    float* sB   = sAT + 2176;            // 16*128         = 2048  floats
    float* sbe2 = sB + 2048;             // 128

    const int tx = threadIdx.x, ty = threadIdx.y;
    const int t  = ty * 16 + tx;
    const int bt = blockIdx.x;           // b tile 0..31
    const int at = blockIdx.y;           // a tile 0..63
    const int b0 = bt * TB;
    const int a0 = at * TA;

    // Load We2 (reused across whole block) and be2
    {
        const float4* src = (const float4*)We2;
        float4* dst = (float4*)sWe2;
#pragma unroll
        for (int i = t; i < 4096; i += 256) dst[i] = src[i];
        if (t < 128) sbe2[t] = be2[t];
    }

    // -------- GEMM1: acc[8][8] over K=256 --------
    float acc[8][8];
#pragma unroll
    for (int i = 0; i < 8; i++)
#pragma unroll
        for (int j = 0; j < 8; j++) acc[i][j] = 0.0f;

    for (int kb = 0; kb < EIN / KT; kb++) {
        __syncthreads();  // protect sAT/sB from previous iteration readers
        // Load edge chunk transposed: sAT[k][m]
#pragma unroll
        for (int r = 0; r < 2; r++) {
            int q = t + r * 256;          // 0..511
            int m = q >> 2;               // 0..127
            int kk = (q & 3) * 4;         // 0,4,8,12
            int a = a0 + (m >> 4);
            int b = b0 + (m & 15);
            float4 v = *(const float4*)&E[(((size_t)a * NB + b) << 8) + kb * KT + kk];
            sAT[(kk + 0) * 136 + m] = v.x;
            sAT[(kk + 1) * 136 + m] = v.y;
            sAT[(kk + 2) * 136 + m] = v.z;
            sAT[(kk + 3) * 136 + m] = v.w;
        }
        // Load We chunk: sB[k][n]  (We = We1 rows 256..511)
#pragma unroll
        for (int r = 0; r < 2; r++) {
            int q = t + r * 256;
            int k = q >> 5;               // 0..15
            int n = (q & 31) * 4;         // 0..124
            *(float4*)&sB[k * NT + n] =
                *(const float4*)&We1[(size_t)(2 * ND + kb * KT + k) * ED + n];
        }
        __syncthreads();
#pragma unroll
        for (int k = 0; k < KT; k++) {
            float av[8], bv[8];
            *(float4*)&av[0] = *(float4*)&sAT[k * 136 + ty * 8];
            *(float4*)&av[4] = *(float4*)&sAT[k * 136 + ty * 8 + 4];
            *(float4*)&bv[0] = *(float4*)&sB[k * NT + tx * 8];
            *(float4*)&bv[4] = *(float4*)&sB[k * NT + tx * 8 + 4];
#pragma unroll
            for (int i = 0; i < 8; i++)
#pragma unroll
                for (int j = 0; j < 8; j++)
                    acc[i][j] = fmaf(av[i], bv[j], acc[i][j]);
        }
    }

    // -------- Epilogue 1: + A1[a] + B1[b], relu, stage h into sL[m][n] --------
    // Thread's 8 rows (m = ty*8+i) all share la = ty>>1; lb = (ty&1)*8 + i.
    const int la = ty >> 1;
    const int ga = a0 + la;
    float arow[8];
    *(float4*)&arow[0] = *(const float4*)&g_A1[(size_t)ga * ED + tx * 8];
    *(float4*)&arow[4] = *(const float4*)&g_A1[(size_t)ga * ED + tx * 8 + 4];
#pragma unroll
    for (int i = 0; i < 8; i++) {
        int lb = (ty & 1) * 8 + i;
        int m = ty * 8 + i;
        float brow[8];
        *(float4*)&brow[0] = *(const float4*)&g_B1[(size_t)(b0 + lb) * ED + tx * 8];
        *(float4*)&brow[4] = *(const float4*)&g_B1[(size_t)(b0 + lb) * ED + tx * 8 + 4];
        float4 h0, h1;
        h0.x = fmaxf(acc[i][0] + arow[0] + brow[0], 0.0f);
        h0.y = fmaxf(acc[i][1] + arow[1] + brow[1], 0.0f);
        h0.z = fmaxf(acc[i][2] + arow[2] + brow[2], 0.0f);
        h0.w = fmaxf(acc[i][3] + arow[3] + brow[3], 0.0f);
        h1.x = fmaxf(acc[i][4] + arow[4] + brow[4], 0.0f);
        h1.y = fmaxf(acc[i][5] + arow[5] + brow[5], 0.0f);
        h1.z = fmaxf(acc[i][6] + arow[6] + brow[6], 0.0f);
        h1.w = fmaxf(acc[i][7] + arow[7] + brow[7], 0.0f);
        *(float4*)&sL[m * 132 + tx * 8]     = h0;
        *(float4*)&sL[m * 132 + tx * 8 + 4] = h1;
    }
    __syncthreads();

    // -------- GEMM2: acc2 = h @ We2, K=128 --------
    float acc2[8][8];
#pragma unroll
    for (int i = 0; i < 8; i++)
#pragma unroll
        for (int j = 0; j < 8; j++) acc2[i][j] = 0.0f;

#pragma unroll 8
    for (int k2 = 0; k2 < ED; k2++) {
        float av[8], bv[8];
#pragma unroll
        for (int i = 0; i < 8; i++) av[i] = sL[(ty * 8 + i) * 132 + k2];  // broadcast reads
        *(float4*)&bv[0] = *(float4*)&sWe2[k2 * NT + tx * 8];
        *(float4*)&bv[4] = *(float4*)&sWe2[k2 * NT + tx * 8 + 4];
#pragma unroll
        for (int i = 0; i < 8; i++)
#pragma unroll
            for (int j = 0; j < 8; j++)
                acc2[i][j] = fmaf(av[i], bv[j], acc2[i][j]);
    }
    __syncthreads();  // all h reads done before sL is overwritten with latent

    // -------- Epilogue 2: + be2, relu, write edge_latent + stage into sL --------
    float b2[8];
    *(float4*)&b2[0] = *(float4*)&sbe2[tx * 8];
    *(float4*)&b2[4] = *(float4*)&sbe2[tx * 8 + 4];
#pragma unroll
    for (int i = 0; i < 8; i++) {
        int lb = (ty & 1) * 8 + i;
        int m = ty * 8 + i;
        float4 v0, v1;
        v0.x = fmaxf(acc2[i][0] + b2[0], 0.0f);
        v0.y = fmaxf(acc2[i][1] + b2[1], 0.0f);
        v0.z = fmaxf(acc2[i][2] + b2[2], 0.0f);
        v0.w = fmaxf(acc2[i][3] + b2[3], 0.0f);
        v1.x = fmaxf(acc2[i][4] + b2[4], 0.0f);
        v1.y = fmaxf(acc2[i][5] + b2[5], 0.0f);
        v1.z = fmaxf(acc2[i][6] + b2[6], 0.0f);
        v1.w = fmaxf(acc2[i][7] + b2[7], 0.0f);
        size_t row = ((size_t)ga * NB + (b0 + lb)) * (size_t)ED;
        *(float4*)&out[row + tx * 8]     = v0;
        *(float4*)&out[row + tx * 8 + 4] = v1;
        *(float4*)&sL[m * 132 + tx * 8]     = v0;
        *(float4*)&sL[m * 132 + tx * 8 + 4] = v1;
    }
    __syncthreads();

    // -------- Deterministic in-block partial reductions --------
    // sum over b (within tile) -> per (la, n) : 8*128 = 1024 tasks
    for (int q = t; q < TA * ED; q += 256) {
        int la2 = q >> 7;
        int n = q & 127;
        float s = 0.0f;
#pragma unroll
        for (int lb = 0; lb < TB; lb++) s += sL[(la2 * TB + lb) * 132 + n];
        g_sumA_part[((size_t)(a0 + la2) * 32 + bt) * ED + n] = s;
    }
    // sum over a (within tile) -> per (lb, n) : 16*128 = 2048 tasks
    for (int q = t; q < TB * ED; q += 256) {
        int lb2 = q >> 7;
        int n = q & 127;
        float s = 0.0f;
#pragma unroll
        for (int la2 = 0; la2 < TA; la2++) s += sL[(la2 * TB + lb2) * 132 + n];
        g_sumB_part[((size_t)(b0 + lb2) * 64 + at) * ED + n] = s;
    }
}

// ---------------------------------------------------------------------------
// Kernel 3: final reduction of partial sums + node MLPs.
// grid 1024 blocks (512 a rows, then 512 b rows), 128 threads.
// ---------------------------------------------------------------------------
__global__ void k_node(const float* __restrict__ na, const float* __restrict__ nb,
                       const float* __restrict__ Wn1, const float* __restrict__ bn1,
                       const float* __restrict__ Wn2, const float* __restrict__ bn2,
                       float* __restrict__ out) {
    int r = blockIdx.x;
    int d = threadIdx.x;
    bool isA = (r < NA);
    int rr = isA ? r : r - NA;
    __shared__ float xs[2 * ND];
    __shared__ float h1[ND];
    xs[d] = (isA ? na : nb)[rr * ND + d];
    float s = 0.0f;
    if (isA) {
        const float* p = g_sumA_part + (size_t)rr * 32 * ED + d;
#pragma unroll
        for (int tt = 0; tt < 32; tt++) s += p[(size_t)tt * ED];
    } else {
        const float* p = g_sumB_part + (size_t)rr * 64 * ED + d;
#pragma unroll
        for (int tt = 0; tt < 64; tt++) s += p[(size_t)tt * ED];
    }
    xs[ND + d] = s;
    __syncthreads();
    float acc = bn1[d];
#pragma unroll 8
    for (int k = 0; k < 2 * ND; k++) acc = fmaf(xs[k], Wn1[k * ND + d], acc);
    h1[d] = fmaxf(acc, 0.0f);
    __syncthreads();
    float acc2 = bn2[d];
#pragma unroll 8
    for (int k = 0; k < ND; k++) acc2 = fmaf(h1[k], Wn2[k * ND + d], acc2);
    size_t off = (size_t)NA * NB * ED + (isA ? 0 : (size_t)NA * ND) + (size_t)rr * ND + d;
    out[off] = fmaxf(acc2, 0.0f);
}

// ---------------------------------------------------------------------------
extern "C" void kernel_launch(void* const* d_in, const int* in_sizes, int n_in,
                              void* d_out, int out_size) {
    const float* edge = (const float*)d_in[0];   // (512,512,256)
    const float* na   = (const float*)d_in[1];   // (512,128)
    const float* nb   = (const float*)d_in[2];   // (512,128)
    const float* We1  = (const float*)d_in[3];   // (512,128)
    const float* be1  = (const float*)d_in[4];   // (128)
    const float* We2  = (const float*)d_in[5];   // (128,128)
    const float* be2  = (const float*)d_in[6];   // (128)
    const float* Wn1  = (const float*)d_in[7];   // (256,128)
    const float* bn1  = (const float*)d_in[8];   // (128)
    const float* Wn2  = (const float*)d_in[9];   // (128,128)
    const float* bn2  = (const float*)d_in[10];  // (128)
    float* out = (float*)d_out;

    // Precompute A1/B1
    k_pre<<<NA + NB, ND>>>(na, nb, We1, be1);

    // Main edge kernel: 32 b-tiles x 64 a-tiles
    const int smem_bytes = (16384 + 16896 + 2176 + 2048 + 128) * (int)sizeof(float);
    cudaFuncSetAttribute(k_edge, cudaFuncAttributeMaxDynamicSharedMemorySize, smem_bytes);
    dim3 grid(NB / TB, NA / TA);
    dim3 block(16, 16);
    k_edge<<<grid, block, smem_bytes>>>(edge, We1, We2, be2, out);

    // Final sums + node MLPs
    k_node<<<NA + NB, ND>>>(na, nb, Wn1, bn1, Wn2, bn2, out);
}

// round 4
// speedup vs baseline: 1.8161x; 1.8161x over previous
#include <cuda_runtime.h>
#include <cuda_bf16.h>
#include <cstdint>

#define NA 512
#define NB 512
#define ND 128
#define ED 128

#define PADB 144          // bytes per 64-bf16 row (72 bf16) -> conflict-free frags
#define TILEB 18432       // 128 * 144

// ---------------- device scratch ----------------
__device__ float g_A1[NA * ED];
__device__ float g_B1[NB * ED];
__device__ float g_sumA_part[(size_t)NA * 32 * ED];
__device__ float g_sumB_part[(size_t)NB * 64 * ED];
// bf16 hi/lo weight images, padded layout [n][72 bf16] per 64-k chunk
__device__ __align__(16) char g_WeB[4 * 2 * TILEB];    // We^T  4 chunks: [hi|lo]
__device__ __align__(16) char g_We2B[2 * 2 * TILEB];   // We2^T 2 chunks: [hi|lo]

// ---------------- helpers ----------------
__device__ __forceinline__ void split2(float f0, float f1, uint32_t& hi, uint32_t& lo) {
    uint32_t h;
    asm("cvt.rn.bf16x2.f32 %0, %1, %2;" : "=r"(h) : "f"(f1), "f"(f0));  // low half = f0
    float r0 = f0 - __uint_as_float(h << 16);
    float r1 = f1 - __uint_as_float(h & 0xffff0000u);
    uint32_t l;
    asm("cvt.rn.bf16x2.f32 %0, %1, %2;" : "=r"(l) : "f"(r1), "f"(r0));
    hi = h; lo = l;
}

__device__ __forceinline__ void mma16816(float* c, const uint32_t* a, uint32_t b0, uint32_t b1) {
    asm volatile(
        "mma.sync.aligned.m16n8k16.row.col.f32.bf16.bf16.f32 "
        "{%0,%1,%2,%3}, {%4,%5,%6,%7}, {%8,%9}, {%0,%1,%2,%3};"
        : "+f"(c[0]), "+f"(c[1]), "+f"(c[2]), "+f"(c[3])
        : "r"(a[0]), "r"(a[1]), "r"(a[2]), "r"(a[3]), "r"(b0), "r"(b1));
}

// ---------------- SMEM layout (bytes) ----------------
#define R1      0          // 4*TILEB = 73728 : GEMM1 {Ah|Al|Bh|Bl}; then h {Hh0|Hl0|Hh1|Hl1}; then sL
#define R2      73728      // 4*TILEB = 73728 : We2 {hi0|lo0|hi1|lo1}
#define SM_A1   147456     // 8*132*4  = 4224
#define SM_B1   151680     // 16*132*4 = 8448
#define SM_BE2  160128     // 512
#define SM_TOTAL 160640

// ---------------------------------------------------------------------------
// k_pre: A1 = na@Wa + be1 ; B1 = nb@Wb. 128 blocks x 128 threads, 8 rows each.
// ---------------------------------------------------------------------------
__global__ void k_pre(const float* __restrict__ na, const float* __restrict__ nb,
                      const float* __restrict__ We1, const float* __restrict__ be1) {
    int blk = blockIdx.x;
    bool isA = blk < 64;
    int r0 = (isA ? blk : blk - 64) * 8;
    const float* X = isA ? na : nb;
    const float* W = We1 + (isA ? 0 : ND) * ED;
    __shared__ float xs[8][ND];
    int d = threadIdx.x;
    for (int i = d; i < 8 * ND; i += 128) xs[i >> 7][i & 127] = X[(r0 + (i >> 7)) * ND + (i & 127)];
    __syncthreads();
    float acc[8];
    float bb = isA ? be1[d] : 0.0f;
#pragma unroll
    for (int i = 0; i < 8; i++) acc[i] = bb;
#pragma unroll 4
    for (int k = 0; k < ND; k++) {
        float w = W[k * ED + d];
#pragma unroll
        for (int i = 0; i < 8; i++) acc[i] = fmaf(xs[i][k], w, acc[i]);
    }
    float* dst = isA ? g_A1 : g_B1;
#pragma unroll
    for (int i = 0; i < 8; i++) dst[(r0 + i) * ED + d] = acc[i];
}

// ---------------------------------------------------------------------------
// k_prepw: bf16 hi/lo images of We^T (4 chunks) and We2^T (2 chunks), padded.
// ---------------------------------------------------------------------------
__global__ void k_prepw(const float* __restrict__ We1, const float* __restrict__ We2) {
    int idx = blockIdx.x * 256 + threadIdx.x;   // 192*256 = 49152
    float x; char* base; int n, j;
    if (idx < 32768) {                           // We^T: 4 x 128n x 64k
        int c = idx >> 13; int r = idx & 8191;
        n = r >> 6; j = r & 63;
        x = We1[(size_t)(2 * ND + c * 64 + j) * ED + n];
        base = g_WeB + c * 2 * TILEB;
    } else {
        int i2 = idx - 32768;                    // We2^T: 2 x 128n x 64k
        int c = i2 >> 13; int r = i2 & 8191;
        n = r >> 6; j = r & 63;
        x = We2[(size_t)(c * 64 + j) * ED + n];
        base = g_We2B + c * 2 * TILEB;
    }
    __nv_bfloat16 h = __float2bfloat16(x);
    __nv_bfloat16 l = __float2bfloat16(x - __bfloat162float(h));
    *(__nv_bfloat16*)(base + n * PADB + j * 2) = h;
    *(__nv_bfloat16*)(base + TILEB + n * PADB + j * 2) = l;
}

// ---------------------------------------------------------------------------
// load E chunk (128 edges x 64 fp32) -> split bf16 hi/lo into padded smem
// ---------------------------------------------------------------------------
__device__ __forceinline__ void load_E_chunk(const float* __restrict__ E, int a0, int b0,
                                             int c, char* Ah, char* Al, int t) {
#pragma unroll
    for (int it = 0; it < 4; it++) {
        int u = t + it * 256;             // 0..1023
        int m = u >> 3;
        int g = u & 7;
        int a = a0 + (m >> 4), b = b0 + (m & 15);
        const float* src = E + (((size_t)(a * NB + b)) << 8) + c * 64 + g * 8;
        float4 v0 = *(const float4*)src;
        float4 v1 = *(const float4*)(src + 4);
        uint32_t h0, l0, h1, l1, h2, l2, h3, l3;
        split2(v0.x, v0.y, h0, l0); split2(v0.z, v0.w, h1, l1);
        split2(v1.x, v1.y, h2, l2); split2(v1.z, v1.w, h3, l3);
        *(uint4*)(Ah + m * PADB + g * 16) = make_uint4(h0, h1, h2, h3);
        *(uint4*)(Al + m * PADB + g * 16) = make_uint4(l0, l1, l2, l3);
    }
}

// 4 k16-steps of a 64-k chunk, 3-term split MMA
__device__ __forceinline__ void gemm_chunk(const char* Ah, const char* Al,
                                           const char* Bh, const char* Bl,
                                           float acc[2][8][4],
                                           int wm, int wn, int lr, int lc) {
#pragma unroll
    for (int kk = 0; kk < 64; kk += 16) {
        uint32_t ah[2][4], al[2][4];
#pragma unroll
        for (int i = 0; i < 2; i++) {
            int rb = (wm * 32 + i * 16 + lr) * PADB + (kk + lc * 2) * 2;
            ah[i][0] = *(const uint32_t*)(Ah + rb);
            ah[i][1] = *(const uint32_t*)(Ah + rb + 8 * PADB);
            ah[i][2] = *(const uint32_t*)(Ah + rb + 16);
            ah[i][3] = *(const uint32_t*)(Ah + rb + 8 * PADB + 16);
            al[i][0] = *(const uint32_t*)(Al + rb);
            al[i][1] = *(const uint32_t*)(Al + rb + 8 * PADB);
            al[i][2] = *(const uint32_t*)(Al + rb + 16);
            al[i][3] = *(const uint32_t*)(Al + rb + 8 * PADB + 16);
        }
#pragma unroll
        for (int j = 0; j < 8; j++) {
            int nb_ = (wn * 64 + j * 8 + lr) * PADB + (kk + lc * 2) * 2;
            uint32_t bh0 = *(const uint32_t*)(Bh + nb_);
            uint32_t bh1 = *(const uint32_t*)(Bh + nb_ + 16);
            uint32_t bl0 = *(const uint32_t*)(Bl + nb_);
            uint32_t bl1 = *(const uint32_t*)(Bl + nb_ + 16);
#pragma unroll
            for (int i = 0; i < 2; i++) {
                mma16816(acc[i][j], ah[i], bh0, bh1);
                mma16816(acc[i][j], al[i], bh0, bh1);
                mma16816(acc[i][j], ah[i], bl0, bl1);
            }
        }
    }
}

// ---------------------------------------------------------------------------
// k_edge: HMMA pipeline. 256 threads, tile = 8a x 16b = 128 edges x 128 dims.
// ---------------------------------------------------------------------------
__global__ __launch_bounds__(256, 1)
void k_edge(const float* __restrict__ E, const float* __restrict__ be2,
            float* __restrict__ out) {
    extern __shared__ char sm[];
    const int t = threadIdx.x, lane = t & 31, wid = t >> 5;
    const int wm = wid >> 1, wn = wid & 1;
    const int lr = lane >> 2, lc = lane & 3;
    const int bt = blockIdx.x, at = blockIdx.y;
    const int b0 = bt * 16, a0 = at * 8;

    float* sA1 = (float*)(sm + SM_A1);
    float* sB1 = (float*)(sm + SM_B1);
    float* sbe2 = (float*)(sm + SM_BE2);

    // staging: We2 blobs, A1/B1 rows, be2
    {
        const uint4* src = (const uint4*)g_We2B;
        uint4* dst = (uint4*)(sm + R2);
        for (int i = t; i < 4608; i += 256) dst[i] = src[i];
    }
    for (int i = t; i < 8 * ED; i += 256)  sA1[(i >> 7) * 132 + (i & 127)] = g_A1[(a0 + (i >> 7)) * ED + (i & 127)];
    for (int i = t; i < 16 * ED; i += 256) sB1[(i >> 7) * 132 + (i & 127)] = g_B1[(b0 + (i >> 7)) * ED + (i & 127)];
    if (t < 128) sbe2[t] = be2[t];

    char* Ah = sm + R1;
    char* Al = Ah + TILEB;
    char* Bh = Al + TILEB;
    char* Bl = Bh + TILEB;

    float acc[2][8][4];
#pragma unroll
    for (int i = 0; i < 2; i++)
#pragma unroll
        for (int j = 0; j < 8; j++)
#pragma unroll
            for (int q = 0; q < 4; q++) acc[i][j][q] = 0.0f;

    // ---------------- GEMM1: 4 K-chunks ----------------
    for (int c = 0; c < 4; c++) {
        if (c) __syncthreads();           // previous chunk's reads complete
        load_E_chunk(E, a0, b0, c, Ah, Al, t);
        {
            const uint4* src = (const uint4*)(g_WeB + c * 2 * TILEB);
            uint4* dst = (uint4*)Bh;      // Bh|Bl contiguous 2*TILEB
            for (int i = t; i < 2304; i += 256) dst[i] = src[i];
        }
        __syncthreads();
        gemm_chunk(Ah, Al, Bh, Bl, acc, wm, wn, lr, lc);
    }
    __syncthreads();  // all GEMM1 smem reads done before h overwrites R1

    // ---------------- epilogue 1: h = relu(D + A1 + B1) -> split into R1 ----------------
    {
        char* Hh = sm + R1 + wn * 2 * TILEB;   // chunk wn (cols wn*64..+63)
        char* Hl = Hh + TILEB;
#pragma unroll
        for (int i = 0; i < 2; i++) {
#pragma unroll
            for (int j = 0; j < 8; j++) {
                int m0 = wm * 32 + i * 16 + lr;
                int col = wn * 64 + j * 8 + lc * 2;
                int cc2 = (col & 63) * 2;
                float f0 = fmaxf(acc[i][j][0] + sA1[(m0 >> 4) * 132 + col] + sB1[(m0 & 15) * 132 + col], 0.0f);
                float f1 = fmaxf(acc[i][j][1] + sA1[(m0 >> 4) * 132 + col + 1] + sB1[(m0 & 15) * 132 + col + 1], 0.0f);
                uint32_t hi, lo;
                split2(f0, f1, hi, lo);
                *(uint32_t*)(Hh + m0 * PADB + cc2) = hi;
                *(uint32_t*)(Hl + m0 * PADB + cc2) = lo;
                int m1 = m0 + 8;
                f0 = fmaxf(acc[i][j][2] + sA1[(m1 >> 4) * 132 + col] + sB1[(m1 & 15) * 132 + col], 0.0f);
                f1 = fmaxf(acc[i][j][3] + sA1[(m1 >> 4) * 132 + col + 1] + sB1[(m1 & 15) * 132 + col + 1], 0.0f);
                split2(f0, f1, hi, lo);
                *(uint32_t*)(Hh + m1 * PADB + cc2) = hi;
                *(uint32_t*)(Hl + m1 * PADB + cc2) = lo;
            }
        }
    }
    __syncthreads();

    // ---------------- GEMM2: h @ We2, 2 K-chunks ----------------
#pragma unroll
    for (int i = 0; i < 2; i++)
#pragma unroll
        for (int j = 0; j < 8; j++)
#pragma unroll
            for (int q = 0; q < 4; q++) acc[i][j][q] = 0.0f;

#pragma unroll
    for (int c2 = 0; c2 < 2; c2++) {
        const char* HAh = sm + R1 + c2 * 2 * TILEB;
        const char* HAl = HAh + TILEB;
        const char* WBh = sm + R2 + c2 * 2 * TILEB;
        const char* WBl = WBh + TILEB;
        gemm_chunk(HAh, HAl, WBh, WBl, acc, wm, wn, lr, lc);
    }
    __syncthreads();  // all h/We2 reads done before sL overwrites R1

    // ---------------- epilogue 2: L = relu(D + be2) -> sL ----------------
    float* sL = (float*)(sm + R1);   // 128 x 132 fp32
#pragma unroll
    for (int i = 0; i < 2; i++) {
#pragma unroll
        for (int j = 0; j < 8; j++) {
            int m0 = wm * 32 + i * 16 + lr;
            int col = wn * 64 + j * 8 + lc * 2;
            sL[m0 * 132 + col]     = fmaxf(acc[i][j][0] + sbe2[col],     0.0f);
            sL[m0 * 132 + col + 1] = fmaxf(acc[i][j][1] + sbe2[col + 1], 0.0f);
            int m1 = m0 + 8;
            sL[m1 * 132 + col]     = fmaxf(acc[i][j][2] + sbe2[col],     0.0f);
            sL[m1 * 132 + col + 1] = fmaxf(acc[i][j][3] + sbe2[col + 1], 0.0f);
        }
    }
    __syncthreads();

    // ---------------- coalesced out writes ----------------
    for (int i = t; i < 4096; i += 256) {       // 128 rows x 32 float4
        int m = i >> 5;
        int cg = (i & 31) * 4;
        int ga = a0 + (m >> 4), gb = b0 + (m & 15);
        *(float4*)&out[((size_t)(ga * NB + gb)) * ED + cg] = *(float4*)&sL[m * 132 + cg];
    }

    // ---------------- deterministic partial reductions ----------------
    for (int q = t; q < 8 * ED; q += 256) {
        int la2 = q >> 7, n = q & 127;
        float s = 0.0f;
#pragma unroll
        for (int lb2 = 0; lb2 < 16; lb2++) s += sL[(la2 * 16 + lb2) * 132 + n];
        g_sumA_part[((size_t)(a0 + la2) * 32 + bt) * ED + n] = s;
    }
    for (int q = t; q < 16 * ED; q += 256) {
        int lb2 = q >> 7, n = q & 127;
        float s = 0.0f;
#pragma unroll
        for (int la2 = 0; la2 < 8; la2++) s += sL[(la2 * 16 + lb2) * 132 + n];
        g_sumB_part[((size_t)(b0 + lb2) * 64 + at) * ED + n] = s;
    }
}

// ---------------------------------------------------------------------------
// k_node: reduce partials + node MLPs.
// ---------------------------------------------------------------------------
__global__ void k_node(const float* __restrict__ na, const float* __restrict__ nb,
                       const float* __restrict__ Wn1, const float* __restrict__ bn1,
                       const float* __restrict__ Wn2, const float* __restrict__ bn2,
                       float* __restrict__ out) {
    int r = blockIdx.x;
    int d = threadIdx.x;
    bool isA = (r < NA);
    int rr = isA ? r : r - NA;
    __shared__ float xs[2 * ND];
    __shared__ float h1[ND];
    xs[d] = (isA ? na : nb)[rr * ND + d];
    float s = 0.0f;
    if (isA) {
        const float* p = g_sumA_part + (size_t)rr * 32 * ED + d;
#pragma unroll
        for (int tt = 0; tt < 32; tt++) s += p[(size_t)tt * ED];
    } else {
        const float* p = g_sumB_part + (size_t)rr * 64 * ED + d;
#pragma unroll
        for (int tt = 0; tt < 64; tt++) s += p[(size_t)tt * ED];
    }
    xs[ND + d] = s;
    __syncthreads();
    float acc = bn1[d];
#pragma unroll 8
    for (int k = 0; k < 2 * ND; k++) acc = fmaf(xs[k], Wn1[k * ND + d], acc);
    h1[d] = fmaxf(acc, 0.0f);
    __syncthreads();
    float acc2 = bn2[d];
#pragma unroll 8
    for (int k = 0; k < ND; k++) acc2 = fmaf(h1[k], Wn2[k * ND + d], acc2);
    size_t off = (size_t)NA * NB * ED + (isA ? 0 : (size_t)NA * ND) + (size_t)rr * ND + d;
    out[off] = fmaxf(acc2, 0.0f);
}

// ---------------------------------------------------------------------------
extern "C" void kernel_launch(void* const* d_in, const int* in_sizes, int n_in,
                              void* d_out, int out_size) {
    const float* edge = (const float*)d_in[0];
    const float* na   = (const float*)d_in[1];
    const float* nb   = (const float*)d_in[2];
    const float* We1  = (const float*)d_in[3];
    const float* be1  = (const float*)d_in[4];
    const float* We2  = (const float*)d_in[5];
    const float* be2  = (const float*)d_in[6];
    const float* Wn1  = (const float*)d_in[7];
    const float* bn1  = (const float*)d_in[8];
    const float* Wn2  = (const float*)d_in[9];
    const float* bn2  = (const float*)d_in[10];
    float* out = (float*)d_out;

    k_pre<<<128, 128>>>(na, nb, We1, be1);
    k_prepw<<<192, 256>>>(We1, We2);

    static int smem_set = 0;
    if (!smem_set) {
        cudaFuncSetAttribute(k_edge, cudaFuncAttributeMaxDynamicSharedMemorySize, SM_TOTAL);
        smem_set = 1;
    }
    dim3 grid(NB / 16, NA / 8);
    k_edge<<<grid, 256, SM_TOTAL>>>(edge, be2, out);

    k_node<<<NA + NB, 128>>>(na, nb, Wn1, bn1, Wn2, bn2, out);
}

// round 7
// speedup vs baseline: 2.2119x; 1.2179x over previous
#include <cuda_runtime.h>
#include <cuda_bf16.h>
#include <cstdint>

#define NA 512
#define NB 512
#define ND 128
#define ED 128

#define PADB 144
#define TILEB 18432        // 128 * 144

// ---------------- device scratch ----------------
__device__ float g_A1[NA * ED];
__device__ float g_B1[NB * ED];
__device__ float g_sumA_part[(size_t)NA * 32 * ED];
__device__ float g_sumB_part[(size_t)NB * 64 * ED];
__device__ __align__(16) char g_WeB[4 * 2 * TILEB];    // We^T  4 chunks: [hi|lo]
__device__ __align__(16) char g_We2B[2 * 2 * TILEB];   // We2^T 2 chunks: [hi|lo]

// ---------------- helpers ----------------
__device__ __forceinline__ uint32_t smem_u32(const void* p) {
    uint32_t a;
    asm("{ .reg .u64 t; cvta.to.shared.u64 t, %1; cvt.u32.u64 %0, t; }" : "=r"(a) : "l"(p));
    return a;
}
__device__ __forceinline__ void split2(float f0, float f1, uint32_t& hi, uint32_t& lo) {
    uint32_t h;
    asm("cvt.rn.bf16x2.f32 %0, %1, %2;" : "=r"(h) : "f"(f1), "f"(f0));
    float r0 = f0 - __uint_as_float(h << 16);
    float r1 = f1 - __uint_as_float(h & 0xffff0000u);
    uint32_t l;
    asm("cvt.rn.bf16x2.f32 %0, %1, %2;" : "=r"(l) : "f"(r1), "f"(r0));
    hi = h; lo = l;
}
__device__ __forceinline__ void mma16816(float* c, const uint32_t* a, uint32_t b0, uint32_t b1) {
    asm volatile(
        "mma.sync.aligned.m16n8k16.row.col.f32.bf16.bf16.f32 "
        "{%0,%1,%2,%3}, {%4,%5,%6,%7}, {%8,%9}, {%0,%1,%2,%3};"
        : "+f"(c[0]), "+f"(c[1]), "+f"(c[2]), "+f"(c[3])
        : "r"(a[0]), "r"(a[1]), "r"(a[2]), "r"(a[3]), "r"(b0), "r"(b1));
}
__device__ __forceinline__ void ldsm4(uint32_t* r, uint32_t addr) {
    asm volatile("ldmatrix.sync.aligned.m8n8.x4.shared.b16 {%0,%1,%2,%3}, [%4];"
                 : "=r"(r[0]), "=r"(r[1]), "=r"(r[2]), "=r"(r[3]) : "r"(addr));
}
#define CP16(dst, src) asm volatile("cp.async.cg.shared.global [%0], [%1], 16;" :: "r"(dst), "l"(src))
#define CP_COMMIT()    asm volatile("cp.async.commit_group;" ::: "memory")
#define CP_WAIT(n)     asm volatile("cp.async.wait_group %0;" :: "n"(n) : "memory")

// ---------------- SMEM layout (bytes) ----------------
#define ABUF    0                       // 2*TILEB = 36864 : {Ah|Al}, then h chunk0
#define BBUF    36864                   // 2 stages x 2*TILEB = 73728 ; s0 reused for h chunk1
#define WE2     110592                  // 4*TILEB = 73728 : {hi0|lo0|hi1|lo1}
#define SM_A1   184320                  // 8*132*4  = 4224
#define SM_B1   188544                  // 16*132*4 = 8448
#define SM_BE2  196992                  // 512
#define SM_TOTAL 197504
// sL overlay at ABUF: 128*132*4 = 67584 bytes (fits in ABUF+BBUF span)

// ---------------------------------------------------------------------------
// k_prep: fused k_pre + k_prepw. 320 blocks x 256 threads.
// ---------------------------------------------------------------------------
__global__ void k_prep(const float* __restrict__ na, const float* __restrict__ nb,
                       const float* __restrict__ We1, const float* __restrict__ be1,
                       const float* __restrict__ We2w) {
    if (blockIdx.x < 128) {
        int blk = blockIdx.x;
        bool isA = blk < 64;
        int r0 = (isA ? blk : blk - 64) * 8;
        const float* X = isA ? na : nb;
        const float* W = We1 + (isA ? 0 : ND) * ED;
        __shared__ float xs[8][ND];
        int t = threadIdx.x;
        for (int i = t; i < 8 * ND; i += 256) xs[i >> 7][i & 127] = X[(r0 + (i >> 7)) * ND + (i & 127)];
        __syncthreads();
        if (t < 128) {
            int d = t;
            float acc[8];
            float bb = isA ? be1[d] : 0.0f;
#pragma unroll
            for (int i = 0; i < 8; i++) acc[i] = bb;
#pragma unroll 4
            for (int k = 0; k < ND; k++) {
                float w = W[k * ED + d];
#pragma unroll
                for (int i = 0; i < 8; i++) acc[i] = fmaf(xs[i][k], w, acc[i]);
            }
            float* dst = isA ? g_A1 : g_B1;
#pragma unroll
            for (int i = 0; i < 8; i++) dst[(r0 + i) * ED + d] = acc[i];
        }
    } else {
        int idx = (blockIdx.x - 128) * 256 + threadIdx.x;   // 0..49151
        float x; char* base; int n, j;
        if (idx < 32768) {
            int c = idx >> 13; int r = idx & 8191;
            n = r >> 6; j = r & 63;
            x = We1[(size_t)(2 * ND + c * 64 + j) * ED + n];
            base = g_WeB + c * 2 * TILEB;
        } else {
            int i2 = idx - 32768;
            int c = i2 >> 13; int r = i2 & 8191;
            n = r >> 6; j = r & 63;
            x = We2w[(size_t)(c * 64 + j) * ED + n];
            base = g_We2B + c * 2 * TILEB;
        }
        __nv_bfloat16 h = __float2bfloat16(x);
        __nv_bfloat16 l = __float2bfloat16(x - __bfloat162float(h));
        *(__nv_bfloat16*)(base + n * PADB + j * 2) = h;
        *(__nv_bfloat16*)(base + TILEB + n * PADB + j * 2) = l;
    }
}

// ---------------------------------------------------------------------------
// E-chunk prefetch (LDG->regs) and split-store (regs->smem)
// ---------------------------------------------------------------------------
__device__ __forceinline__ void ldgA(float4* pf, const float* __restrict__ E,
                                     int a0, int b0, int c, int t) {
#pragma unroll
    for (int it = 0; it < 4; it++) {
        int u = t + it * 256;
        int m = u >> 3, g = u & 7;
        int a = a0 + (m >> 4), b = b0 + (m & 15);
        const float4* src = (const float4*)(E + (((size_t)(a * NB + b)) << 8) + c * 64 + g * 8);
        pf[it * 2]     = __ldg(src);
        pf[it * 2 + 1] = __ldg(src + 1);
    }
}
__device__ __forceinline__ void stsA(const float4* pf, char* Ah, char* Al, int t) {
#pragma unroll
    for (int it = 0; it < 4; it++) {
        int u = t + it * 256;
        int m = u >> 3, g = u & 7;
        float4 v0 = pf[it * 2], v1 = pf[it * 2 + 1];
        uint32_t h0, l0, h1, l1, h2, l2, h3, l3;
        split2(v0.x, v0.y, h0, l0); split2(v0.z, v0.w, h1, l1);
        split2(v1.x, v1.y, h2, l2); split2(v1.z, v1.w, h3, l3);
        *(uint4*)(Ah + m * PADB + g * 16) = make_uint4(h0, h1, h2, h3);
        *(uint4*)(Al + m * PADB + g * 16) = make_uint4(l0, l1, l2, l3);
    }
}

// ---------------------------------------------------------------------------
// one 64-k chunk of 3-term split GEMM via ldmatrix + mma
// aAh/aAl: per-lane A addr (hi/lo); aBh/aBl: per-lane B addr (hi/lo)
// ---------------------------------------------------------------------------
__device__ __forceinline__ void gemm_chunk(uint32_t aAh, uint32_t aAl,
                                           uint32_t aBh, uint32_t aBl,
                                           float acc[2][8][4]) {
#pragma unroll
    for (int kk = 0; kk < 4; kk++) {
        uint32_t ah[2][4], al[2][4];
        ldsm4(ah[0], aAh + kk * 32);
        ldsm4(ah[1], aAh + 16 * PADB + kk * 32);
        ldsm4(al[0], aAl + kk * 32);
        ldsm4(al[1], aAl + 16 * PADB + kk * 32);
#pragma unroll
        for (int jp = 0; jp < 4; jp++) {
            uint32_t bh[4], bl[4];
            ldsm4(bh, aBh + jp * 16 * PADB + kk * 32);
            ldsm4(bl, aBl + jp * 16 * PADB + kk * 32);
#pragma unroll
            for (int i = 0; i < 2; i++) {
                mma16816(acc[i][2 * jp],     ah[i], bh[0], bh[1]);
                mma16816(acc[i][2 * jp],     al[i], bh[0], bh[1]);
                mma16816(acc[i][2 * jp],     ah[i], bl[0], bl[1]);
                mma16816(acc[i][2 * jp + 1], ah[i], bh[2], bh[3]);
                mma16816(acc[i][2 * jp + 1], al[i], bh[2], bh[3]);
                mma16816(acc[i][2 * jp + 1], ah[i], bl[2], bl[3]);
            }
        }
    }
}

// ---------------------------------------------------------------------------
// k_edge
// ---------------------------------------------------------------------------
__global__ __launch_bounds__(256, 1)
void k_edge(const float* __restrict__ E, const float* __restrict__ be2,
            float* __restrict__ out) {
    extern __shared__ char sm[];
    const int t = threadIdx.x, lane = t & 31, wid = t >> 5;
    const int wm = wid >> 1, wn = wid & 1;
    const int lr = lane >> 2, lc = lane & 3;
    const int bt = blockIdx.x, at = blockIdx.y;
    const int b0 = bt * 16, a0 = at * 8;

    float* sA1 = (float*)(sm + SM_A1);
    float* sB1 = (float*)(sm + SM_B1);
    float* sbe2 = (float*)(sm + SM_BE2);
    const uint32_t smb = smem_u32(sm);

    // per-lane ldmatrix offsets
    const uint32_t aoff = (uint32_t)((wm * 32 + (lane & 15)) * PADB + (lane >> 4) * 16);
    const uint32_t boff = (uint32_t)((wn * 64 + (lane & 7) + ((lane >> 4) << 3)) * PADB
                                     + ((lane >> 3) & 1) * 16);

    // ---- prologue: B0 + We2 via cp.async, A0 via LDG+split ----
    for (int i = t; i < 2304; i += 256)
        CP16(smb + BBUF + i * 16, g_WeB + i * 16);
    CP_COMMIT();
    for (int i = t; i < 4608; i += 256)
        CP16(smb + WE2 + i * 16, g_We2B + i * 16);
    CP_COMMIT();

    float4 pf[8];
    ldgA(pf, E, a0, b0, 0, t);
    stsA(pf, sm + ABUF, sm + ABUF + TILEB, t);

    for (int i = t; i < 8 * ED; i += 256)  sA1[(i >> 7) * 132 + (i & 127)] = g_A1[(a0 + (i >> 7)) * ED + (i & 127)];
    for (int i = t; i < 16 * ED; i += 256) sB1[(i >> 7) * 132 + (i & 127)] = g_B1[(b0 + (i >> 7)) * ED + (i & 127)];
    if (t < 128) sbe2[t] = be2[t];

    CP_WAIT(1);        // B0 arrived (We2 may be in flight)
    __syncthreads();

    float acc[2][8][4];
#pragma unroll
    for (int i = 0; i < 2; i++)
#pragma unroll
        for (int j = 0; j < 8; j++)
#pragma unroll
            for (int q = 0; q < 4; q++) acc[i][j][q] = 0.0f;

    // ---- GEMM1: 4 k-chunks, A reg-prefetch + B cp.async double-buffer ----
#pragma unroll
    for (int c = 0; c < 4; c++) {
        int s = c & 1;
        if (c < 3) {
            ldgA(pf, E, a0, b0, c + 1, t);
            uint32_t dst = smb + BBUF + (s ^ 1) * 2 * TILEB;
            const char* src = g_WeB + (c + 1) * 2 * TILEB;
            for (int i = t; i < 2304; i += 256)
                CP16(dst + i * 16, src + i * 16);
            CP_COMMIT();
        }
        uint32_t bb = smb + BBUF + s * 2 * TILEB;
        gemm_chunk(smb + ABUF + aoff, smb + ABUF + TILEB + aoff,
                   bb + boff, bb + TILEB + boff, acc);
        __syncthreads();
        if (c < 3) {
            stsA(pf, sm + ABUF, sm + ABUF + TILEB, t);
            CP_WAIT(0);
            __syncthreads();
        }
    }

    // ---- epilogue 1: h = relu(D + A1 + B1) -> split into ABUF (chunk0) / BBUF (chunk1) ----
    {
        char* Hh = (wn == 0) ? (sm + ABUF) : (sm + BBUF);
        char* Hl = Hh + TILEB;
#pragma unroll
        for (int i = 0; i < 2; i++) {
#pragma unroll
            for (int j = 0; j < 8; j++) {
                int m0 = wm * 32 + i * 16 + lr;
                int col = wn * 64 + j * 8 + lc * 2;
                int cc2 = (col & 63) * 2;
                float f0 = fmaxf(acc[i][j][0] + sA1[(m0 >> 4) * 132 + col]     + sB1[(m0 & 15) * 132 + col],     0.0f);
                float f1 = fmaxf(acc[i][j][1] + sA1[(m0 >> 4) * 132 + col + 1] + sB1[(m0 & 15) * 132 + col + 1], 0.0f);
                uint32_t hi, lo;
                split2(f0, f1, hi, lo);
                *(uint32_t*)(Hh + m0 * PADB + cc2) = hi;
                *(uint32_t*)(Hl + m0 * PADB + cc2) = lo;
                int m1 = m0 + 8;
                f0 = fmaxf(acc[i][j][2] + sA1[(m1 >> 4) * 132 + col]     + sB1[(m1 & 15) * 132 + col],     0.0f);
                f1 = fmaxf(acc[i][j][3] + sA1[(m1 >> 4) * 132 + col + 1] + sB1[(m1 & 15) * 132 + col + 1], 0.0f);
                split2(f0, f1, hi, lo);
                *(uint32_t*)(Hh + m1 * PADB + cc2) = hi;
                *(uint32_t*)(Hl + m1 * PADB + cc2) = lo;
            }
        }
    }
    __syncthreads();

    // ---- GEMM2: h @ We2, 2 k-chunks ----
#pragma unroll
    for (int i = 0; i < 2; i++)
#pragma unroll
        for (int j = 0; j < 8; j++)
#pragma unroll
            for (int q = 0; q < 4; q++) acc[i][j][q] = 0.0f;

#pragma unroll
    for (int c2 = 0; c2 < 2; c2++) {
        uint32_t ha = smb + ((c2 == 0) ? ABUF : BBUF);
        uint32_t wb = smb + WE2 + c2 * 2 * TILEB;
        gemm_chunk(ha + aoff, ha + TILEB + aoff, wb + boff, wb + TILEB + boff, acc);
    }
    __syncthreads();

    // ---- epilogue 2: L = relu(D + be2) -> sL ----
    float* sL = (float*)(sm + ABUF);   // 128 x 132 fp32 overlay
#pragma unroll
    for (int i = 0; i < 2; i++) {
#pragma unroll
        for (int j = 0; j < 8; j++) {
            int m0 = wm * 32 + i * 16 + lr;
            int col = wn * 64 + j * 8 + lc * 2;
            sL[m0 * 132 + col]     = fmaxf(acc[i][j][0] + sbe2[col],     0.0f);
            sL[m0 * 132 + col + 1] = fmaxf(acc[i][j][1] + sbe2[col + 1], 0.0f);
            int m1 = m0 + 8;
            sL[m1 * 132 + col]     = fmaxf(acc[i][j][2] + sbe2[col],     0.0f);
            sL[m1 * 132 + col + 1] = fmaxf(acc[i][j][3] + sbe2[col + 1], 0.0f);
        }
    }
    __syncthreads();

    // ---- coalesced out writes ----
    for (int i = t; i < 4096; i += 256) {
        int m = i >> 5;
        int cg = (i & 31) * 4;
        int ga = a0 + (m >> 4), gb = b0 + (m & 15);
        *(float4*)&out[((size_t)(ga * NB + gb)) * ED + cg] = *(float4*)&sL[m * 132 + cg];
    }

    // ---- deterministic partial reductions ----
    for (int q = t; q < 8 * ED; q += 256) {
        int la2 = q >> 7, n = q & 127;
        float s = 0.0f;
#pragma unroll
        for (int lb2 = 0; lb2 < 16; lb2++) s += sL[(la2 * 16 + lb2) * 132 + n];
        g_sumA_part[((size_t)(a0 + la2) * 32 + bt) * ED + n] = s;
    }
    for (int q = t; q < 16 * ED; q += 256) {
        int lb2 = q >> 7, n = q & 127;
        float s = 0.0f;
#pragma unroll
        for (int la2 = 0; la2 < 8; la2++) s += sL[(la2 * 16 + lb2) * 132 + n];
        g_sumB_part[((size_t)(b0 + lb2) * 64 + at) * ED + n] = s;
    }
}

// ---------------------------------------------------------------------------
// k_node: reduce partials (4-way MLP) + node MLPs.
// ---------------------------------------------------------------------------
__global__ void k_node(const float* __restrict__ na, const float* __restrict__ nb,
                       const float* __restrict__ Wn1, const float* __restrict__ bn1,
                       const float* __restrict__ Wn2, const float* __restrict__ bn2,
                       float* __restrict__ out) {
    int r = blockIdx.x;
    int d = threadIdx.x;
    bool isA = (r < NA);
    int rr = isA ? r : r - NA;
    __shared__ float xs[2 * ND];
    __shared__ float h1[ND];
    xs[d] = (isA ? na : nb)[rr * ND + d];
    float s0 = 0.f, s1 = 0.f, s2 = 0.f, s3 = 0.f;
    if (isA) {
        const float* p = g_sumA_part + (size_t)rr * 32 * ED + d;
#pragma unroll
        for (int tt = 0; tt < 32; tt += 4) {
            s0 += __ldg(p + (size_t)(tt + 0) * ED);
            s1 += __ldg(p + (size_t)(tt + 1) * ED);
            s2 += __ldg(p + (size_t)(tt + 2) * ED);
            s3 += __ldg(p + (size_t)(tt + 3) * ED);
        }
    } else {
        const float* p = g_sumB_part + (size_t)rr * 64 * ED + d;
#pragma unroll
        for (int tt = 0; tt < 64; tt += 4) {
            s0 += __ldg(p + (size_t)(tt + 0) * ED);
            s1 += __ldg(p + (size_t)(tt + 1) * ED);
            s2 += __ldg(p + (size_t)(tt + 2) * ED);
            s3 += __ldg(p + (size_t)(tt + 3) * ED);
        }
    }
    xs[ND + d] = (s0 + s1) + (s2 + s3);
    __syncthreads();
    float acc = bn1[d];
#pragma unroll 8
    for (int k = 0; k < 2 * ND; k++) acc = fmaf(xs[k], Wn1[k * ND + d], acc);
    h1[d] = fmaxf(acc, 0.0f);
    __syncthreads();
    float acc2 = bn2[d];
#pragma unroll 8
    for (int k = 0; k < ND; k++) acc2 = fmaf(h1[k], Wn2[k * ND + d], acc2);
    size_t off = (size_t)NA * NB * ED + (isA ? 0 : (size_t)NA * ND) + (size_t)rr * ND + d;
    out[off] = fmaxf(acc2, 0.0f);
}

// ---------------------------------------------------------------------------
extern "C" void kernel_launch(void* const* d_in, const int* in_sizes, int n_in,
                              void* d_out, int out_size) {
    const float* edge = (const float*)d_in[0];
    const float* na   = (const float*)d_in[1];
    const float* nb   = (const float*)d_in[2];
    const float* We1  = (const float*)d_in[3];
    const float* be1  = (const float*)d_in[4];
    const float* We2  = (const float*)d_in[5];
    const float* be2  = (const float*)d_in[6];
    const float* Wn1  = (const float*)d_in[7];
    const float* bn1  = (const float*)d_in[8];
    const float* Wn2  = (const float*)d_in[9];
    const float* bn2  = (const float*)d_in[10];
    float* out = (float*)d_out;

    k_prep<<<320, 256>>>(na, nb, We1, be1, We2);

    static int smem_set = 0;
    if (!smem_set) {
        cudaFuncSetAttribute(k_edge, cudaFuncAttributeMaxDynamicSharedMemorySize, SM_TOTAL);
        smem_set = 1;
    }
    dim3 grid(NB / 16, NA / 8);
    k_edge<<<grid, 256, SM_TOTAL>>>(edge, be2, out);

    k_node<<<NA + NB, 128>>>(na, nb, Wn1, bn1, Wn2, bn2, out);
}